// round 4
// baseline (speedup 1.0000x reference)
#include <cuda_runtime.h>
#include <cstdint>

// Causal SDPA: B=2, H=16, S=2048, D=128, fp32 in/out.
// Flash-attention, tf32 mma.sync.m16n8k8, online softmax.
//   - Br=128 q rows per CTA (8 warps x 16 rows), Bc=64 kv rows per tile
//   - Q pre-scaled + tf32-rounded, resident in registers (16 k-steps x 4 frags)
//   - K/V double-buffered in smem via cp.async (LDGSTS)
//   - P (exp scores) round-trips through smem to re-fragment for the PV mma

#define B_ 2
#define H_ 16
#define S_ 2048
#define D_ 128

constexpr int BR      = 128;
constexpr int BC      = 64;
constexpr int WARPS   = 8;
constexpr int THREADS = 256;

// smem row strides (floats), padded for conflict-free fragment loads
constexpr int KST = 132;   // (4g+c)%32 distinct for K b-frags
constexpr int VST = 136;   // (8r+g)%32 distinct for V b-frags
constexpr int PST = 68;    // (4g+c)%32 distinct for P a-frags

constexpr int KTILE_F = BC * KST;                       // 8448 floats / stage
constexpr int VTILE_F = BC * VST;                       // 8704 floats / stage
constexpr int SMEM_FLOATS = 2 * KTILE_F + 2 * VTILE_F + BR * PST;  // 43008
constexpr int SMEM_BYTES  = SMEM_FLOATS * 4;            // 172032 B

__device__ __forceinline__ uint32_t f2tf32(float x) {
    uint32_t r;
    asm("cvt.rna.tf32.f32 %0, %1;" : "=r"(r) : "f"(x));
    return r;
}

__device__ __forceinline__ void mma_tf32(float c[4],
                                         uint32_t a0, uint32_t a1, uint32_t a2, uint32_t a3,
                                         uint32_t b0, uint32_t b1) {
    asm volatile(
        "mma.sync.aligned.m16n8k8.row.col.f32.tf32.tf32.f32 "
        "{%0,%1,%2,%3}, {%4,%5,%6,%7}, {%8,%9}, {%0,%1,%2,%3};"
        : "+f"(c[0]), "+f"(c[1]), "+f"(c[2]), "+f"(c[3])
        : "r"(a0), "r"(a1), "r"(a2), "r"(a3), "r"(b0), "r"(b1));
}

__device__ __forceinline__ void cp_async16(uint32_t dst_smem, const void* src) {
    asm volatile("cp.async.cg.shared.global [%0], [%1], 16;" :: "r"(dst_smem), "l"(src));
}

// Issue cp.async for one K tile + one V tile (64 rows x 128 f32 each) and commit.
__device__ __forceinline__ void load_kv_tile(const float* kg, const float* vg,
                                             uint32_t kdst, uint32_t vdst, int tid) {
    // 64 rows x 32 sixteen-byte chunks = 2048 chunks each
    #pragma unroll
    for (int it = 0; it < (BC * (D_ / 4)) / THREADS; ++it) {
        int i = tid + it * THREADS;
        int row = i >> 5, ch = i & 31;
        cp_async16(kdst + (uint32_t)(row * KST + ch * 4) * 4u, kg + row * D_ + ch * 4);
    }
    #pragma unroll
    for (int it = 0; it < (BC * (D_ / 4)) / THREADS; ++it) {
        int i = tid + it * THREADS;
        int row = i >> 5, ch = i & 31;
        cp_async16(vdst + (uint32_t)(row * VST + ch * 4) * 4u, vg + row * D_ + ch * 4);
    }
    asm volatile("cp.async.commit_group;");
}

__global__ __launch_bounds__(THREADS, 1)
void fa_causal_tf32_kernel(const float* __restrict__ q, const float* __restrict__ k,
                           const float* __restrict__ v, float* __restrict__ out) {
    extern __shared__ __align__(16) float smem[];
    float*    ksm = smem;                                   // [2][BC][KST]
    float*    vsm = smem + 2 * KTILE_F;                     // [2][BC][VST]
    uint32_t* psm = (uint32_t*)(smem + 2 * KTILE_F + 2 * VTILE_F);  // [BR][PST]

    const int tid  = threadIdx.x;
    const int w    = tid >> 5;
    const int lane = tid & 31;
    const int g    = lane >> 2;   // group id (rows g, g+8 of mma tile)
    const int c    = lane & 3;    // thread-in-group

    // longest-running q-tiles launch first
    const int qt     = (int)(gridDim.x - 1) - (int)blockIdx.x;
    const int bh     = blockIdx.y;
    const long base  = (long)bh * S_ * D_;
    const int q_base = qt * BR;
    const int njt    = (q_base + BR) / BC;   // number of causal kv tiles
    const int wrow   = q_base + w * 16;      // this warp's first q row

    const float scale = 0.08838834764831845f;   // D^-0.5

    const uint32_t smem_u32 = (uint32_t)__cvta_generic_to_shared(smem);
    const uint32_t k_u32    = smem_u32;
    const uint32_t v_u32    = smem_u32 + (uint32_t)(2 * KTILE_F) * 4u;

    // ---- prologue: start loading tile 0 ----
    load_kv_tile(k + base, v + base, k_u32, v_u32, tid);

    // ---- Q: load, scale, tf32-round into registers (16 k-steps x 4 frags) ----
    uint32_t qreg[16][4];
    {
        const float* qp = q + base;
        const long r0 = wrow + g, r1 = r0 + 8;
        #pragma unroll
        for (int ks = 0; ks < 16; ++ks) {
            int col = ks * 8 + c;
            qreg[ks][0] = f2tf32(qp[r0 * D_ + col]     * scale);
            qreg[ks][1] = f2tf32(qp[r1 * D_ + col]     * scale);
            qreg[ks][2] = f2tf32(qp[r0 * D_ + col + 4] * scale);
            qreg[ks][3] = f2tf32(qp[r1 * D_ + col + 4] * scale);
        }
    }

    float oacc[16][4];
    #pragma unroll
    for (int nt = 0; nt < 16; ++nt)
        oacc[nt][0] = oacc[nt][1] = oacc[nt][2] = oacc[nt][3] = 0.f;
    float m0 = -1e30f, m1 = -1e30f, l0 = 0.f, l1 = 0.f;

    for (int j = 0; j < njt; ++j) {
        const int st = j & 1;
        if (j + 1 < njt) {
            const int ns = (j + 1) & 1;
            load_kv_tile(k + base + (long)(j + 1) * BC * D_,
                         v + base + (long)(j + 1) * BC * D_,
                         k_u32 + (uint32_t)(ns * KTILE_F) * 4u,
                         v_u32 + (uint32_t)(ns * VTILE_F) * 4u, tid);
            asm volatile("cp.async.wait_group 1;");
        } else {
            asm volatile("cp.async.wait_group 0;");
        }
        __syncthreads();

        const float* kt = ksm + st * KTILE_F;
        const float* vt = vsm + st * VTILE_F;
        const int kvb = j * BC;

        // ---- S = Q K^T  (16x64 per warp) ----
        float sacc[8][4];
        #pragma unroll
        for (int nt = 0; nt < 8; ++nt)
            sacc[nt][0] = sacc[nt][1] = sacc[nt][2] = sacc[nt][3] = 0.f;

        #pragma unroll
        for (int nt = 0; nt < 8; ++nt) {
            #pragma unroll
            for (int ks = 0; ks < 16; ++ks) {
                const float* kp = kt + (nt * 8 + g) * KST + ks * 8 + c;
                uint32_t b0 = f2tf32(kp[0]);
                uint32_t b1 = f2tf32(kp[4]);
                mma_tf32(sacc[nt], qreg[ks][0], qreg[ks][1], qreg[ks][2], qreg[ks][3], b0, b1);
            }
        }

        // ---- causal mask (only near-diagonal tiles for this warp) ----
        if (kvb + BC - 1 > wrow) {
            #pragma unroll
            for (int nt = 0; nt < 8; ++nt) {
                #pragma unroll
                for (int idx = 0; idx < 4; ++idx) {
                    int col = kvb + nt * 8 + (c << 1) + (idx & 1);
                    int row = wrow + g + ((idx >> 1) << 3);
                    if (col > row) sacc[nt][idx] = -1e30f;
                }
            }
        }

        // ---- online softmax (rows g and g+8) ----
        float tm0 = -1e30f, tm1 = -1e30f;
        #pragma unroll
        for (int nt = 0; nt < 8; ++nt) {
            tm0 = fmaxf(tm0, fmaxf(sacc[nt][0], sacc[nt][1]));
            tm1 = fmaxf(tm1, fmaxf(sacc[nt][2], sacc[nt][3]));
        }
        tm0 = fmaxf(tm0, __shfl_xor_sync(0xffffffffu, tm0, 1));
        tm0 = fmaxf(tm0, __shfl_xor_sync(0xffffffffu, tm0, 2));
        tm1 = fmaxf(tm1, __shfl_xor_sync(0xffffffffu, tm1, 1));
        tm1 = fmaxf(tm1, __shfl_xor_sync(0xffffffffu, tm1, 2));

        const float nm0 = fmaxf(m0, tm0), nm1 = fmaxf(m1, tm1);
        const float a0 = __expf(m0 - nm0), a1 = __expf(m1 - nm1);
        m0 = nm0; m1 = nm1;

        float ts0 = 0.f, ts1 = 0.f;
        uint32_t* prow0 = psm + (w * 16 + g) * PST;
        uint32_t* prow1 = prow0 + 8 * PST;
        #pragma unroll
        for (int nt = 0; nt < 8; ++nt) {
            float p00 = __expf(sacc[nt][0] - nm0);
            float p01 = __expf(sacc[nt][1] - nm0);
            float p10 = __expf(sacc[nt][2] - nm1);
            float p11 = __expf(sacc[nt][3] - nm1);
            ts0 += p00 + p01;
            ts1 += p10 + p11;
            int cc = nt * 8 + (c << 1);
            prow0[cc]     = f2tf32(p00);
            prow0[cc + 1] = f2tf32(p01);
            prow1[cc]     = f2tf32(p10);
            prow1[cc + 1] = f2tf32(p11);
        }
        ts0 += __shfl_xor_sync(0xffffffffu, ts0, 1);
        ts0 += __shfl_xor_sync(0xffffffffu, ts0, 2);
        ts1 += __shfl_xor_sync(0xffffffffu, ts1, 1);
        ts1 += __shfl_xor_sync(0xffffffffu, ts1, 2);
        l0 = l0 * a0 + ts0;
        l1 = l1 * a1 + ts1;

        #pragma unroll
        for (int nt = 0; nt < 16; ++nt) {
            oacc[nt][0] *= a0; oacc[nt][1] *= a0;
            oacc[nt][2] *= a1; oacc[nt][3] *= a1;
        }

        __syncwarp();   // P smem region is warp-private; order stores before frag loads

        // ---- O += P V  (16x128 per warp) ----
        const uint32_t* pr0 = psm + (w * 16 + g) * PST;
        const uint32_t* pr1 = pr0 + 8 * PST;
        #pragma unroll
        for (int ks = 0; ks < 8; ++ks) {
            uint32_t pa0 = pr0[ks * 8 + c];
            uint32_t pa1 = pr1[ks * 8 + c];
            uint32_t pa2 = pr0[ks * 8 + c + 4];
            uint32_t pa3 = pr1[ks * 8 + c + 4];
            const float* vrow0 = vt + (ks * 8 + c) * VST;
            const float* vrow1 = vt + (ks * 8 + c + 4) * VST;
            #pragma unroll
            for (int nt = 0; nt < 16; ++nt) {
                uint32_t b0 = f2tf32(vrow0[nt * 8 + g]);
                uint32_t b1 = f2tf32(vrow1[nt * 8 + g]);
                mma_tf32(oacc[nt], pa0, pa1, pa2, pa3, b0, b1);
            }
        }

        __syncthreads();  // all warps done with this stage before it is refilled
    }

    // ---- epilogue: normalize and store ----
    const float inv0 = 1.f / l0, inv1 = 1.f / l1;
    float* op = out + base;
    const long r0 = wrow + g, r1 = r0 + 8;
    #pragma unroll
    for (int nt = 0; nt < 16; ++nt) {
        int col = nt * 8 + (c << 1);
        float2 o0 = make_float2(oacc[nt][0] * inv0, oacc[nt][1] * inv0);
        float2 o1 = make_float2(oacc[nt][2] * inv1, oacc[nt][3] * inv1);
        *(float2*)(op + r0 * D_ + col) = o0;
        *(float2*)(op + r1 * D_ + col) = o1;
    }
}

extern "C" void kernel_launch(void* const* d_in, const int* in_sizes, int n_in,
                              void* d_out, int out_size) {
    const float* q = (const float*)d_in[0];
    const float* k = (const float*)d_in[1];
    const float* v = (const float*)d_in[2];
    float* out = (float*)d_out;

    cudaFuncSetAttribute(fa_causal_tf32_kernel,
                         cudaFuncAttributeMaxDynamicSharedMemorySize, SMEM_BYTES);
    dim3 grid(S_ / BR, B_ * H_);
    fa_causal_tf32_kernel<<<grid, THREADS, SMEM_BYTES>>>(q, k, v, out);
}

// round 5
// speedup vs baseline: 1.1419x; 1.1419x over previous
#include <cuda_runtime.h>
#include <cstdint>

// Causal SDPA: B=2, H=16, S=2048, D=128, fp32 in/out.
// R5: prologue kernel pre-converts K/V to tf32 into __device__ scratch
//     (eliminates 8x-redundant cvt.rna.tf32 from the hot loop), plus
//     fully-masked warp-tile skipping. Core: flash-attention with
//     tf32 mma.sync.m16n8k8, online softmax, cp.async double buffering.

#define B_ 2
#define H_ 16
#define S_ 2048
#define D_ 128

constexpr int BR      = 128;
constexpr int BC      = 64;
constexpr int THREADS = 256;

// smem row strides (uint32 units), padded for conflict-free fragment loads
constexpr int KST = 132;   // (4g+c)%32 distinct for K b-frags
constexpr int VST = 136;   // (8r+g)%32 distinct for V b-frags
constexpr int PST = 68;    // (4g+c)%32 distinct for P a-frags

constexpr int KTILE_F = BC * KST;                       // 8448 words / stage
constexpr int VTILE_F = BC * VST;                       // 8704 words / stage
constexpr int SMEM_WORDS = 2 * KTILE_F + 2 * VTILE_F + BR * PST;  // 43008
constexpr int SMEM_BYTES = SMEM_WORDS * 4;              // 172032 B

constexpr int KV_ELEMS = B_ * H_ * S_ * D_;             // 8,388,608 per tensor

// tf32-converted K/V scratch (static device arrays: allocation-free).
__device__ __align__(16) uint32_t g_ktf[KV_ELEMS];
__device__ __align__(16) uint32_t g_vtf[KV_ELEMS];

__device__ __forceinline__ uint32_t f2tf32(float x) {
    uint32_t r;
    asm("cvt.rna.tf32.f32 %0, %1;" : "=r"(r) : "f"(x));
    return r;
}

// ---------------------------------------------------------------------------
// Prologue: K,V -> tf32 (one pass, vectorized). ~128MB traffic, ~16us.
// ---------------------------------------------------------------------------
__global__ void __launch_bounds__(256)
cvt_kv_kernel(const float4* __restrict__ k, const float4* __restrict__ v) {
    const int n = KV_ELEMS / 4;
    uint4* kd = reinterpret_cast<uint4*>(g_ktf);
    uint4* vd = reinterpret_cast<uint4*>(g_vtf);
    for (int i = blockIdx.x * blockDim.x + threadIdx.x; i < n;
         i += gridDim.x * blockDim.x) {
        float4 a = k[i];
        uint4 ra;
        ra.x = f2tf32(a.x); ra.y = f2tf32(a.y);
        ra.z = f2tf32(a.z); ra.w = f2tf32(a.w);
        kd[i] = ra;
        float4 b = v[i];
        uint4 rb;
        rb.x = f2tf32(b.x); rb.y = f2tf32(b.y);
        rb.z = f2tf32(b.z); rb.w = f2tf32(b.w);
        vd[i] = rb;
    }
}

// ---------------------------------------------------------------------------
// Main flash-attention kernel
// ---------------------------------------------------------------------------
__device__ __forceinline__ void mma_tf32(float c[4],
                                         uint32_t a0, uint32_t a1, uint32_t a2, uint32_t a3,
                                         uint32_t b0, uint32_t b1) {
    asm volatile(
        "mma.sync.aligned.m16n8k8.row.col.f32.tf32.tf32.f32 "
        "{%0,%1,%2,%3}, {%4,%5,%6,%7}, {%8,%9}, {%0,%1,%2,%3};"
        : "+f"(c[0]), "+f"(c[1]), "+f"(c[2]), "+f"(c[3])
        : "r"(a0), "r"(a1), "r"(a2), "r"(a3), "r"(b0), "r"(b1));
}

__device__ __forceinline__ void cp_async16(uint32_t dst_smem, const void* src) {
    asm volatile("cp.async.cg.shared.global [%0], [%1], 16;" :: "r"(dst_smem), "l"(src));
}

// Issue cp.async for one K tile + one V tile (64 rows x 128 words) and commit.
__device__ __forceinline__ void load_kv_tile(const uint32_t* kg, const uint32_t* vg,
                                             uint32_t kdst, uint32_t vdst, int tid) {
    #pragma unroll
    for (int it = 0; it < (BC * (D_ / 4)) / THREADS; ++it) {
        int i = tid + it * THREADS;
        int row = i >> 5, ch = i & 31;
        cp_async16(kdst + (uint32_t)(row * KST + ch * 4) * 4u, kg + row * D_ + ch * 4);
    }
    #pragma unroll
    for (int it = 0; it < (BC * (D_ / 4)) / THREADS; ++it) {
        int i = tid + it * THREADS;
        int row = i >> 5, ch = i & 31;
        cp_async16(vdst + (uint32_t)(row * VST + ch * 4) * 4u, vg + row * D_ + ch * 4);
    }
    asm volatile("cp.async.commit_group;");
}

__global__ __launch_bounds__(THREADS, 1)
void fa_causal_tf32_kernel(const float* __restrict__ q, float* __restrict__ out) {
    extern __shared__ __align__(16) uint32_t smem[];
    uint32_t* ksm = smem;                                   // [2][BC][KST]
    uint32_t* vsm = smem + 2 * KTILE_F;                     // [2][BC][VST]
    uint32_t* psm = smem + 2 * KTILE_F + 2 * VTILE_F;       // [BR][PST]

    const int tid  = threadIdx.x;
    const int w    = tid >> 5;
    const int lane = tid & 31;
    const int g    = lane >> 2;   // group id (rows g, g+8 of mma tile)
    const int c    = lane & 3;    // thread-in-group

    // longest-running q-tiles launch first
    const int qt     = (int)(gridDim.x - 1) - (int)blockIdx.x;
    const int bh     = blockIdx.y;
    const long base  = (long)bh * S_ * D_;
    const int q_base = qt * BR;
    const int njt    = (q_base + BR) / BC;   // number of causal kv tiles
    const int wrow   = q_base + w * 16;      // this warp's first q row

    const float scale = 0.08838834764831845f;   // D^-0.5

    const uint32_t smem_u32 = (uint32_t)__cvta_generic_to_shared(smem);
    const uint32_t k_u32    = smem_u32;
    const uint32_t v_u32    = smem_u32 + (uint32_t)(2 * KTILE_F) * 4u;

    // ---- prologue: start loading tile 0 ----
    load_kv_tile(g_ktf + base, g_vtf + base, k_u32, v_u32, tid);

    // ---- Q: load, scale, tf32-round into registers (16 k-steps x 4 frags) ----
    uint32_t qreg[16][4];
    {
        const float* qp = q + base;
        const long r0 = wrow + g, r1 = r0 + 8;
        #pragma unroll
        for (int ks = 0; ks < 16; ++ks) {
            int col = ks * 8 + c;
            qreg[ks][0] = f2tf32(qp[r0 * D_ + col]     * scale);
            qreg[ks][1] = f2tf32(qp[r1 * D_ + col]     * scale);
            qreg[ks][2] = f2tf32(qp[r0 * D_ + col + 4] * scale);
            qreg[ks][3] = f2tf32(qp[r1 * D_ + col + 4] * scale);
        }
    }

    float oacc[16][4];
    #pragma unroll
    for (int nt = 0; nt < 16; ++nt)
        oacc[nt][0] = oacc[nt][1] = oacc[nt][2] = oacc[nt][3] = 0.f;
    float m0 = -1e30f, m1 = -1e30f, l0 = 0.f, l1 = 0.f;

    for (int j = 0; j < njt; ++j) {
        const int st = j & 1;
        if (j + 1 < njt) {
            const int ns = (j + 1) & 1;
            load_kv_tile(g_ktf + base + (long)(j + 1) * BC * D_,
                         g_vtf + base + (long)(j + 1) * BC * D_,
                         k_u32 + (uint32_t)(ns * KTILE_F) * 4u,
                         v_u32 + (uint32_t)(ns * VTILE_F) * 4u, tid);
            asm volatile("cp.async.wait_group 1;");
        } else {
            asm volatile("cp.async.wait_group 0;");
        }
        __syncthreads();

        const int kvb = j * BC;

        // Skip warp-tiles that are entirely above the diagonal (fully masked).
        if (wrow + 15 >= kvb) {
            const uint32_t* kt = ksm + st * KTILE_F;
            const uint32_t* vt = vsm + st * VTILE_F;

            // ---- S = Q K^T  (16x64 per warp) ----
            float sacc[8][4];
            #pragma unroll
            for (int nt = 0; nt < 8; ++nt)
                sacc[nt][0] = sacc[nt][1] = sacc[nt][2] = sacc[nt][3] = 0.f;

            #pragma unroll
            for (int nt = 0; nt < 8; ++nt) {
                #pragma unroll
                for (int ks = 0; ks < 16; ++ks) {
                    const uint32_t* kp = kt + (nt * 8 + g) * KST + ks * 8 + c;
                    mma_tf32(sacc[nt], qreg[ks][0], qreg[ks][1], qreg[ks][2], qreg[ks][3],
                             kp[0], kp[4]);
                }
            }

            // ---- causal mask (only near-diagonal tiles for this warp) ----
            if (kvb + BC - 1 > wrow) {
                #pragma unroll
                for (int nt = 0; nt < 8; ++nt) {
                    #pragma unroll
                    for (int idx = 0; idx < 4; ++idx) {
                        int col = kvb + nt * 8 + (c << 1) + (idx & 1);
                        int row = wrow + g + ((idx >> 1) << 3);
                        if (col > row) sacc[nt][idx] = -1e30f;
                    }
                }
            }

            // ---- online softmax (rows g and g+8) ----
            float tm0 = -1e30f, tm1 = -1e30f;
            #pragma unroll
            for (int nt = 0; nt < 8; ++nt) {
                tm0 = fmaxf(tm0, fmaxf(sacc[nt][0], sacc[nt][1]));
                tm1 = fmaxf(tm1, fmaxf(sacc[nt][2], sacc[nt][3]));
            }
            tm0 = fmaxf(tm0, __shfl_xor_sync(0xffffffffu, tm0, 1));
            tm0 = fmaxf(tm0, __shfl_xor_sync(0xffffffffu, tm0, 2));
            tm1 = fmaxf(tm1, __shfl_xor_sync(0xffffffffu, tm1, 1));
            tm1 = fmaxf(tm1, __shfl_xor_sync(0xffffffffu, tm1, 2));

            const float nm0 = fmaxf(m0, tm0), nm1 = fmaxf(m1, tm1);
            const float a0 = __expf(m0 - nm0), a1 = __expf(m1 - nm1);
            m0 = nm0; m1 = nm1;

            float ts0 = 0.f, ts1 = 0.f;
            uint32_t* prow0 = psm + (w * 16 + g) * PST;
            uint32_t* prow1 = prow0 + 8 * PST;
            #pragma unroll
            for (int nt = 0; nt < 8; ++nt) {
                float p00 = __expf(sacc[nt][0] - nm0);
                float p01 = __expf(sacc[nt][1] - nm0);
                float p10 = __expf(sacc[nt][2] - nm1);
                float p11 = __expf(sacc[nt][3] - nm1);
                ts0 += p00 + p01;
                ts1 += p10 + p11;
                int cc = nt * 8 + (c << 1);
                prow0[cc]     = f2tf32(p00);
                prow0[cc + 1] = f2tf32(p01);
                prow1[cc]     = f2tf32(p10);
                prow1[cc + 1] = f2tf32(p11);
            }
            ts0 += __shfl_xor_sync(0xffffffffu, ts0, 1);
            ts0 += __shfl_xor_sync(0xffffffffu, ts0, 2);
            ts1 += __shfl_xor_sync(0xffffffffu, ts1, 1);
            ts1 += __shfl_xor_sync(0xffffffffu, ts1, 2);
            l0 = l0 * a0 + ts0;
            l1 = l1 * a1 + ts1;

            #pragma unroll
            for (int nt = 0; nt < 16; ++nt) {
                oacc[nt][0] *= a0; oacc[nt][1] *= a0;
                oacc[nt][2] *= a1; oacc[nt][3] *= a1;
            }

            __syncwarp();   // P region is warp-private; order stores before frag loads

            // ---- O += P V  (16x128 per warp) ----
            const uint32_t* pr0 = psm + (w * 16 + g) * PST;
            const uint32_t* pr1 = pr0 + 8 * PST;
            #pragma unroll
            for (int ks = 0; ks < 8; ++ks) {
                uint32_t pa0 = pr0[ks * 8 + c];
                uint32_t pa1 = pr1[ks * 8 + c];
                uint32_t pa2 = pr0[ks * 8 + c + 4];
                uint32_t pa3 = pr1[ks * 8 + c + 4];
                const uint32_t* vrow0 = vt + (ks * 8 + c) * VST;
                const uint32_t* vrow1 = vt + (ks * 8 + c + 4) * VST;
                #pragma unroll
                for (int nt = 0; nt < 16; ++nt) {
                    mma_tf32(oacc[nt], pa0, pa1, pa2, pa3,
                             vrow0[nt * 8 + g], vrow1[nt * 8 + g]);
                }
            }
        }

        __syncthreads();  // all warps done with this stage before it is refilled
    }

    // ---- epilogue: normalize and store ----
    const float inv0 = 1.f / l0, inv1 = 1.f / l1;
    float* op = out + base;
    const long r0 = wrow + g, r1 = r0 + 8;
    #pragma unroll
    for (int nt = 0; nt < 16; ++nt) {
        int col = nt * 8 + (c << 1);
        float2 o0 = make_float2(oacc[nt][0] * inv0, oacc[nt][1] * inv0);
        float2 o1 = make_float2(oacc[nt][2] * inv1, oacc[nt][3] * inv1);
        *(float2*)(op + r0 * D_ + col) = o0;
        *(float2*)(op + r1 * D_ + col) = o1;
    }
}

extern "C" void kernel_launch(void* const* d_in, const int* in_sizes, int n_in,
                              void* d_out, int out_size) {
    const float* q = (const float*)d_in[0];
    const float* k = (const float*)d_in[1];
    const float* v = (const float*)d_in[2];
    float* out = (float*)d_out;

    // Prologue: convert K,V to tf32 once (dedup of per-warp cvt in hot loop).
    cvt_kv_kernel<<<2048, 256>>>((const float4*)k, (const float4*)v);

    cudaFuncSetAttribute(fa_causal_tf32_kernel,
                         cudaFuncAttributeMaxDynamicSharedMemorySize, SMEM_BYTES);
    dim3 grid(S_ / BR, B_ * H_);
    fa_causal_tf32_kernel<<<grid, THREADS, SMEM_BYTES>>>(q, out);
}

// round 6
// speedup vs baseline: 1.8696x; 1.6373x over previous
#include <cuda_runtime.h>
#include <cuda_fp16.h>
#include <cstdint>

// Causal SDPA: B=2, H=16, S=2048, D=128, fp32 in/out.
// R6: full fp16 datapath (same 10-bit mantissa as tf32) with f32 accumulation.
//   - mma.sync.m16n8k16.f32.f16.f16.f32 : halves smem traffic AND mma count
//   - prologue converts K -> fp16 and V -> fp16 TRANSPOSED per head (VT[d][s])
//     so both K and V b-fragments are contiguous half2 loads from smem
//   - flash attention, online softmax, cp.async double buffering

#define B_ 2
#define H_ 16
#define S_ 2048
#define D_ 128

constexpr int BR      = 128;
constexpr int BC      = 64;
constexpr int THREADS = 256;

// smem row strides in 32-bit words, chosen so fragment loads hit bank (4g+c)%32
constexpr int KSTW = 68;   // K tile row: 128 halfs + pad  (68 % 32 == 4)
constexpr int VSTW = 36;   // VT tile row: 64 halfs + pad  (36 % 32 == 4)
constexpr int PSTW = 36;   // P tile row:  64 halfs + pad

constexpr int KTILE_W = BC * KSTW;    // 4352 words / stage
constexpr int VTILE_W = D_ * VSTW;    // 4608 words / stage (VT has D_ rows)
constexpr int PTILE_W = BR * PSTW;    // 4608 words
constexpr int SMEM_WORDS = 2 * KTILE_W + 2 * VTILE_W + PTILE_W;  // 22528
constexpr int SMEM_BYTES = SMEM_WORDS * 4;                        // 90112 B

constexpr int KV_ELEMS = B_ * H_ * S_ * D_;   // 8,388,608 per tensor

// fp16 scratch (static device arrays: allocation-free). 16MB each.
__device__ __align__(16) __half g_kth[KV_ELEMS];
__device__ __align__(16) __half g_vth[KV_ELEMS];   // per-head transposed: [bh][d][s]

// ---------------------------------------------------------------------------
// Prologue 1: K -> fp16, same layout. Vectorized float4 -> 4 halfs.
// ---------------------------------------------------------------------------
__global__ void __launch_bounds__(256)
cvt_k_kernel(const float4* __restrict__ k) {
    const int n = KV_ELEMS / 4;
    uint2* kd = reinterpret_cast<uint2*>(g_kth);
    for (int i = blockIdx.x * blockDim.x + threadIdx.x; i < n;
         i += gridDim.x * blockDim.x) {
        float4 a = k[i];
        __half2 lo = __floats2half2_rn(a.x, a.y);
        __half2 hi = __floats2half2_rn(a.z, a.w);
        uint2 o;
        o.x = *(uint32_t*)&lo;
        o.y = *(uint32_t*)&hi;
        kd[i] = o;
    }
}

// ---------------------------------------------------------------------------
// Prologue 2: V -> fp16, transposed per (b,h): VT[d][s] = V[s][d].
// smem-tiled 32x32 transpose, coalesced both sides.
// ---------------------------------------------------------------------------
__global__ void __launch_bounds__(256)
transpose_v_kernel(const float* __restrict__ v) {
    __shared__ __half tile[32][33];
    const int bh = blockIdx.z;
    const int s0 = blockIdx.x * 32;
    const int d0 = blockIdx.y * 32;
    const float* vp = v + (long)bh * S_ * D_;
    __half* vtp = g_vth + (long)bh * (long)D_ * S_;
    const int tx = threadIdx.x, ty = threadIdx.y;
    #pragma unroll
    for (int r = 0; r < 4; ++r) {
        int si = ty + r * 8;
        tile[si][tx] = __float2half_rn(vp[(long)(s0 + si) * D_ + d0 + tx]);
    }
    __syncthreads();
    #pragma unroll
    for (int r = 0; r < 4; ++r) {
        int di = ty + r * 8;
        vtp[(long)(d0 + di) * S_ + s0 + tx] = tile[tx][di];
    }
}

// ---------------------------------------------------------------------------
// Main flash-attention kernel
// ---------------------------------------------------------------------------
__device__ __forceinline__ void mma_f16(float c[4],
                                        uint32_t a0, uint32_t a1, uint32_t a2, uint32_t a3,
                                        uint32_t b0, uint32_t b1) {
    asm volatile(
        "mma.sync.aligned.m16n8k16.row.col.f32.f16.f16.f32 "
        "{%0,%1,%2,%3}, {%4,%5,%6,%7}, {%8,%9}, {%0,%1,%2,%3};"
        : "+f"(c[0]), "+f"(c[1]), "+f"(c[2]), "+f"(c[3])
        : "r"(a0), "r"(a1), "r"(a2), "r"(a3), "r"(b0), "r"(b1));
}

__device__ __forceinline__ void cp_async16(uint32_t dst_smem, const void* src) {
    asm volatile("cp.async.cg.shared.global [%0], [%1], 16;" :: "r"(dst_smem), "l"(src));
}

__device__ __forceinline__ uint32_t pack2(float a, float b) {
    __half2 h = __floats2half2_rn(a, b);
    return *(uint32_t*)&h;
}

// Load one K tile (BC rows x 128 halfs) + one VT tile (128 rows x BC halfs).
__device__ __forceinline__ void load_kv_tile(const __half* kg, const __half* vtg,
                                             uint32_t kdst, uint32_t vdst, int tid) {
    // K: 64 rows x 16 chunks(16B)
    #pragma unroll
    for (int it = 0; it < (BC * 16) / THREADS; ++it) {
        int i = tid + it * THREADS;
        int row = i >> 4, ch = i & 15;
        cp_async16(kdst + (uint32_t)(row * KSTW + ch * 4) * 4u, kg + row * D_ + ch * 8);
    }
    // VT: 128 rows x 8 chunks(16B); row stride in gmem is full S_
    #pragma unroll
    for (int it = 0; it < (D_ * 8) / THREADS; ++it) {
        int i = tid + it * THREADS;
        int row = i >> 3, ch = i & 7;
        cp_async16(vdst + (uint32_t)(row * VSTW + ch * 4) * 4u, vtg + (long)row * S_ + ch * 8);
    }
    asm volatile("cp.async.commit_group;");
}

__global__ __launch_bounds__(THREADS, 1)
void fa_causal_f16_kernel(const float* __restrict__ q, float* __restrict__ out) {
    extern __shared__ __align__(16) uint32_t smem[];
    uint32_t* ksm = smem;                                   // [2][BC][KSTW]
    uint32_t* vsm = smem + 2 * KTILE_W;                     // [2][D_][VSTW]
    uint32_t* psm = smem + 2 * KTILE_W + 2 * VTILE_W;       // [BR][PSTW]

    const int tid  = threadIdx.x;
    const int w    = tid >> 5;
    const int lane = tid & 31;
    const int g    = lane >> 2;   // group id (rows g, g+8 of mma tile)
    const int c    = lane & 3;    // thread-in-group

    // longest-running q-tiles launch first
    const int qt     = (int)(gridDim.x - 1) - (int)blockIdx.x;
    const int bh     = blockIdx.y;
    const long base  = (long)bh * S_ * D_;
    const int q_base = qt * BR;
    const int njt    = (q_base + BR) / BC;   // number of causal kv tiles
    const int wrow   = q_base + w * 16;      // this warp's first q row

    const float scale = 0.08838834764831845f;   // D^-0.5

    const uint32_t smem_u32 = (uint32_t)__cvta_generic_to_shared(smem);
    const uint32_t k_u32    = smem_u32;
    const uint32_t v_u32    = smem_u32 + (uint32_t)(2 * KTILE_W) * 4u;

    const __half* kg  = g_kth + base;            // [s][d]
    const __half* vtg = g_vth + base;            // [d][s]

    // ---- start loading tile 0 ----
    load_kv_tile(kg, vtg, k_u32, v_u32, tid);

    // ---- Q: load, scale, pack to half2 a-frags (8 k-steps x 4 frags) ----
    uint32_t qreg[8][4];
    {
        const float* qp = q + base;
        const long r0 = wrow + g, r1 = r0 + 8;
        #pragma unroll
        for (int ks = 0; ks < 8; ++ks) {
            int col = ks * 16 + 2 * c;
            qreg[ks][0] = pack2(qp[r0 * D_ + col]     * scale, qp[r0 * D_ + col + 1] * scale);
            qreg[ks][1] = pack2(qp[r1 * D_ + col]     * scale, qp[r1 * D_ + col + 1] * scale);
            qreg[ks][2] = pack2(qp[r0 * D_ + col + 8] * scale, qp[r0 * D_ + col + 9] * scale);
            qreg[ks][3] = pack2(qp[r1 * D_ + col + 8] * scale, qp[r1 * D_ + col + 9] * scale);
        }
    }

    float oacc[16][4];
    #pragma unroll
    for (int nt = 0; nt < 16; ++nt)
        oacc[nt][0] = oacc[nt][1] = oacc[nt][2] = oacc[nt][3] = 0.f;
    float m0 = -1e30f, m1 = -1e30f, l0 = 0.f, l1 = 0.f;

    for (int j = 0; j < njt; ++j) {
        const int st = j & 1;
        if (j + 1 < njt) {
            const int ns = (j + 1) & 1;
            load_kv_tile(kg + (long)(j + 1) * BC * D_,
                         vtg + (j + 1) * BC,     // VT: advance along s (columns)
                         k_u32 + (uint32_t)(ns * KTILE_W) * 4u,
                         v_u32 + (uint32_t)(ns * VTILE_W) * 4u, tid);
            asm volatile("cp.async.wait_group 1;");
        } else {
            asm volatile("cp.async.wait_group 0;");
        }
        __syncthreads();

        const int kvb = j * BC;

        // Skip warp-tiles entirely above the diagonal (fully masked).
        if (wrow + 15 >= kvb) {
            const uint32_t* kt = ksm + st * KTILE_W;
            const uint32_t* vt = vsm + st * VTILE_W;

            // ---- S = Q K^T  (16x64 per warp, 8x8 mmas) ----
            float sacc[8][4];
            #pragma unroll
            for (int nt = 0; nt < 8; ++nt)
                sacc[nt][0] = sacc[nt][1] = sacc[nt][2] = sacc[nt][3] = 0.f;

            #pragma unroll
            for (int nt = 0; nt < 8; ++nt) {
                const uint32_t* kp = kt + (nt * 8 + g) * KSTW + c;
                #pragma unroll
                for (int ks = 0; ks < 8; ++ks) {
                    mma_f16(sacc[nt], qreg[ks][0], qreg[ks][1], qreg[ks][2], qreg[ks][3],
                            kp[ks * 8], kp[ks * 8 + 4]);
                }
            }

            // ---- causal mask (near-diagonal tiles only) ----
            if (kvb + BC - 1 > wrow) {
                #pragma unroll
                for (int nt = 0; nt < 8; ++nt) {
                    #pragma unroll
                    for (int idx = 0; idx < 4; ++idx) {
                        int col = kvb + nt * 8 + (c << 1) + (idx & 1);
                        int row = wrow + g + ((idx >> 1) << 3);
                        if (col > row) sacc[nt][idx] = -1e30f;
                    }
                }
            }

            // ---- online softmax (rows g and g+8) ----
            float tm0 = -1e30f, tm1 = -1e30f;
            #pragma unroll
            for (int nt = 0; nt < 8; ++nt) {
                tm0 = fmaxf(tm0, fmaxf(sacc[nt][0], sacc[nt][1]));
                tm1 = fmaxf(tm1, fmaxf(sacc[nt][2], sacc[nt][3]));
            }
            tm0 = fmaxf(tm0, __shfl_xor_sync(0xffffffffu, tm0, 1));
            tm0 = fmaxf(tm0, __shfl_xor_sync(0xffffffffu, tm0, 2));
            tm1 = fmaxf(tm1, __shfl_xor_sync(0xffffffffu, tm1, 1));
            tm1 = fmaxf(tm1, __shfl_xor_sync(0xffffffffu, tm1, 2));

            const float nm0 = fmaxf(m0, tm0), nm1 = fmaxf(m1, tm1);
            const float a0 = __expf(m0 - nm0), a1 = __expf(m1 - nm1);
            m0 = nm0; m1 = nm1;

            float ts0 = 0.f, ts1 = 0.f;
            uint32_t* prow0 = psm + (w * 16 + g) * PSTW;
            uint32_t* prow1 = prow0 + 8 * PSTW;
            #pragma unroll
            for (int nt = 0; nt < 8; ++nt) {
                float p00 = __expf(sacc[nt][0] - nm0);
                float p01 = __expf(sacc[nt][1] - nm0);
                float p10 = __expf(sacc[nt][2] - nm1);
                float p11 = __expf(sacc[nt][3] - nm1);
                ts0 += p00 + p01;
                ts1 += p10 + p11;
                prow0[nt * 4 + c] = pack2(p00, p01);
                prow1[nt * 4 + c] = pack2(p10, p11);
            }
            ts0 += __shfl_xor_sync(0xffffffffu, ts0, 1);
            ts0 += __shfl_xor_sync(0xffffffffu, ts0, 2);
            ts1 += __shfl_xor_sync(0xffffffffu, ts1, 1);
            ts1 += __shfl_xor_sync(0xffffffffu, ts1, 2);
            l0 = l0 * a0 + ts0;
            l1 = l1 * a1 + ts1;

            #pragma unroll
            for (int nt = 0; nt < 16; ++nt) {
                oacc[nt][0] *= a0; oacc[nt][1] *= a0;
                oacc[nt][2] *= a1; oacc[nt][3] *= a1;
            }

            __syncwarp();   // P rows are warp-private; order stores before frag loads

            // ---- O += P V  (16x128 per warp, 4x16 mmas) ----
            const uint32_t* pr0 = psm + (w * 16 + g) * PSTW;
            const uint32_t* pr1 = pr0 + 8 * PSTW;
            #pragma unroll
            for (int ks = 0; ks < 4; ++ks) {
                uint32_t pa0 = pr0[ks * 8 + c];
                uint32_t pa1 = pr1[ks * 8 + c];
                uint32_t pa2 = pr0[ks * 8 + c + 4];
                uint32_t pa3 = pr1[ks * 8 + c + 4];
                #pragma unroll
                for (int nt = 0; nt < 16; ++nt) {
                    const uint32_t* vp = vt + (nt * 8 + g) * VSTW + ks * 8 + c;
                    mma_f16(oacc[nt], pa0, pa1, pa2, pa3, vp[0], vp[4]);
                }
            }
        }

        __syncthreads();  // all warps done with this stage before refill
    }

    // ---- epilogue: normalize and store ----
    const float inv0 = 1.f / l0, inv1 = 1.f / l1;
    float* op = out + base;
    const long r0 = wrow + g, r1 = r0 + 8;
    #pragma unroll
    for (int nt = 0; nt < 16; ++nt) {
        int col = nt * 8 + (c << 1);
        float2 o0 = make_float2(oacc[nt][0] * inv0, oacc[nt][1] * inv0);
        float2 o1 = make_float2(oacc[nt][2] * inv1, oacc[nt][3] * inv1);
        *(float2*)(op + r0 * D_ + col) = o0;
        *(float2*)(op + r1 * D_ + col) = o1;
    }
}

extern "C" void kernel_launch(void* const* d_in, const int* in_sizes, int n_in,
                              void* d_out, int out_size) {
    const float* q = (const float*)d_in[0];
    const float* k = (const float*)d_in[1];
    const float* v = (const float*)d_in[2];
    float* out = (float*)d_out;

    // Prologue: K -> fp16 (same layout), V -> fp16 transposed per head.
    cvt_k_kernel<<<1024, 256>>>((const float4*)k);
    dim3 tgrid(S_ / 32, D_ / 32, B_ * H_);
    transpose_v_kernel<<<tgrid, dim3(32, 8)>>>(v);

    cudaFuncSetAttribute(fa_causal_f16_kernel,
                         cudaFuncAttributeMaxDynamicSharedMemorySize, SMEM_BYTES);
    dim3 grid(S_ / BR, B_ * H_);
    fa_causal_f16_kernel<<<grid, THREADS, SMEM_BYTES>>>(q, out);
}